// round 9
// baseline (speedup 1.0000x reference)
#include <cuda_runtime.h>
#include <cuda_fp16.h>
#include <cstdint>
#include <cstddef>

// Problem dims: y[b,m,n] = sum_k x[b,m,k] w[k,n]; flatten b,m -> M
#define MDIM 8192
#define KDIM 4096
#define NDIM 4096

// GEMM tiling: CTA 128x128x64, 8 warps (2m x 4n), warp tile 64x32, 4 stages
// fp16-accumulate MMA chained over K=64, promoted to fp32 once per kt.
#define BM 128
#define BN 128
#define BK 64
#define STAGES 4
#define KT (KDIM / BK)  // 64
#define THREADS 256

#define LDA 72   // 64 + 8 pad (fp16 elems per A smem row)
#define LDB 136  // 128 + 8 pad
#define A_TILE_B (BM * LDA * 2)        // 18432
#define B_TILE_B (BK * LDB * 2)        // 17408
#define STAGE_B (A_TILE_B + B_TILE_B)  // 35840
#define SMEM_B (STAGES * STAGE_B)      // 143360 -> 1 CTA/SM

// fp16 scratch (allocation-free rule: __device__ globals)
__device__ __half g_xh[(size_t)MDIM * KDIM];  // 67 MB
__device__ __half g_wh[(size_t)KDIM * NDIM];  // 33.5 MB

static __device__ __forceinline__ uint32_t smem_u32(const void* p) {
    uint32_t a;
    asm("{ .reg .u64 t; cvta.to.shared.u64 t, %1; cvt.u32.u64 %0, t; }"
        : "=r"(a) : "l"(p));
    return a;
}

#define CP_ASYNC16(dst, src) \
    asm volatile("cp.async.cg.shared.global [%0], [%1], 16;" :: "r"(dst), "l"(src))
#define CP_COMMIT() asm volatile("cp.async.commit_group;" ::: "memory")
#define CP_WAIT(n)  asm volatile("cp.async.wait_group %0;" :: "n"(n) : "memory")

#define LDMATRIX_X4(r0, r1, r2, r3, addr)                                  \
    asm volatile("ldmatrix.sync.aligned.m8n8.x4.shared.b16 "               \
                 "{%0,%1,%2,%3}, [%4];"                                    \
                 : "=r"(r0), "=r"(r1), "=r"(r2), "=r"(r3) : "r"(addr))

#define LDMATRIX_X4_T(r0, r1, r2, r3, addr)                                \
    asm volatile("ldmatrix.sync.aligned.m8n8.x4.trans.shared.b16 "         \
                 "{%0,%1,%2,%3}, [%4];"                                    \
                 : "=r"(r0), "=r"(r1), "=r"(r2), "=r"(r3) : "r"(addr))

// fp16-accumulate MMA: D(f16x2 x2) = A*B + D
#define MMA16816_F16(d0, d1, a, b0, b1)                                    \
    asm volatile("mma.sync.aligned.m16n8k16.row.col.f16.f16.f16.f16 "      \
                 "{%0,%1}, {%2,%3,%4,%5}, {%6,%7}, {%0,%1};"               \
                 : "+r"(d0), "+r"(d1)                                      \
                 : "r"((a)[0]), "r"((a)[1]), "r"((a)[2]), "r"((a)[3]),     \
                   "r"(b0), "r"(b1))

// ---------------------------------------------------------------------------
// prep: fused fp32 -> fp16 for both x and w (one launch)
// ---------------------------------------------------------------------------
#define XCHUNKS ((size_t)MDIM * KDIM / 4)  // 8388608 float4s
#define WCHUNKS ((size_t)KDIM * NDIM / 4)  // 4194304 float4s

__global__ void cvt_both_kernel(const float4* __restrict__ x4,
                                const float4* __restrict__ w4) {
    size_t i = (size_t)blockIdx.x * blockDim.x + threadIdx.x;
    const float4* src;
    uint2* dst;
    if (i < XCHUNKS) {
        src = x4 + i;
        dst = reinterpret_cast<uint2*>(g_xh) + i;
    } else {
        src = w4 + (i - XCHUNKS);
        dst = reinterpret_cast<uint2*>(g_wh) + (i - XCHUNKS);
    }
    float4 v = *src;
    __half2 h0 = __floats2half2_rn(v.x, v.y);
    __half2 h1 = __floats2half2_rn(v.z, v.w);
    uint2 o;
    o.x = *reinterpret_cast<uint32_t*>(&h0);
    o.y = *reinterpret_cast<uint32_t*>(&h1);
    *dst = o;
}

// ---------------------------------------------------------------------------
// GEMM: fp16-acc chains of 4 MMAs (K=64) per position, promote to fp32 per kt
// ---------------------------------------------------------------------------
__global__ void __launch_bounds__(THREADS, 1) gemm_kernel(float* __restrict__ out) {
    extern __shared__ char smem_raw[];
    const uint32_t smem = smem_u32(smem_raw);

    const int tid = threadIdx.x;
    const int lane = tid & 31;
    const int wid = tid >> 5;
    const int warp_m = wid & 1;   // 0..1
    const int warp_n = wid >> 1;  // 0..3

    const int m0 = blockIdx.y * BM;
    const int n0 = blockIdx.x * BN;

    const __half* gA = g_xh + (size_t)m0 * KDIM;
    const __half* gB = g_wh + n0;

    // ---- cp.async addresses: A 1024 chunks (4/thread), B 1024 chunks (4/thread)
    uint32_t sA_dst[4];
    const __half* gA_src[4];
#pragma unroll
    for (int i = 0; i < 4; ++i) {
        int c = tid + i * THREADS;
        int row = c >> 3, ch = c & 7;
        sA_dst[i] = smem + (uint32_t)(row * LDA + ch * 8) * 2;
        gA_src[i] = gA + (size_t)row * KDIM + ch * 8;
    }
    uint32_t sB_dst[4];
    const __half* gB_src[4];
#pragma unroll
    for (int i = 0; i < 4; ++i) {
        int c = tid + i * THREADS;
        int row = c >> 4, ch = c & 15;
        sB_dst[i] = smem + A_TILE_B + (uint32_t)(row * LDB + ch * 8) * 2;
        gB_src[i] = gB + (size_t)row * NDIM + ch * 8;
    }

#define ISSUE_STAGE(slot, kt_)                                              \
    do {                                                                    \
        const uint32_t sb = (uint32_t)(slot) * STAGE_B;                     \
        const size_t kb = (size_t)(kt_) * BK;                               \
        _Pragma("unroll")                                                   \
        for (int i = 0; i < 4; ++i)                                         \
            CP_ASYNC16(sA_dst[i] + sb, gA_src[i] + kb);                     \
        _Pragma("unroll")                                                   \
        for (int i = 0; i < 4; ++i)                                         \
            CP_ASYNC16(sB_dst[i] + sb, gB_src[i] + kb * NDIM);              \
    } while (0)

    // ---- fragment base addresses ----
    // A x4: rows warp_m*64 + mi*16 + (lane&15), k-col (lane>>4)*8
    const uint32_t a_frag =
        smem + (uint32_t)((warp_m * 64 + (lane & 15)) * LDA + (lane >> 4) * 8) * 2;
    // B x4.trans: k-rows (lane&15), n-col warp_n*32 + (lane>>4)*8
    const uint32_t b_frag =
        smem + A_TILE_B +
        (uint32_t)((lane & 15) * LDB + warp_n * 32 + (lane >> 4) * 8) * 2;

    float acc[4][4][4];
#pragma unroll
    for (int mi = 0; mi < 4; ++mi)
#pragma unroll
        for (int ni = 0; ni < 4; ++ni)
#pragma unroll
            for (int q = 0; q < 4; ++q) acc[mi][ni][q] = 0.f;

    // ---- prologue ----
#pragma unroll
    for (int s = 0; s < STAGES - 1; ++s) {
        ISSUE_STAGE(s, s);
        CP_COMMIT();
    }

    // ---- mainloop ----
    int s_cur = 0;
    int s_nxt = STAGES - 1;
    for (int kt = 0; kt < KT; ++kt) {
        CP_WAIT(STAGES - 2);
        __syncthreads();

        if (kt + STAGES - 1 < KT) ISSUE_STAGE(s_nxt, kt + STAGES - 1);
        CP_COMMIT();

        const uint32_t sb = (uint32_t)s_cur * STAGE_B;
        const uint32_t aB = a_frag + sb;
        const uint32_t bB = b_frag + sb;

        // Load ALL B fragments for this kt first (B[kk][g]: g = 16-col group)
        uint32_t B[4][2][4];
#pragma unroll
        for (int kk = 0; kk < 4; ++kk)
#pragma unroll
            for (int g = 0; g < 2; ++g)
                LDMATRIX_X4_T(B[kk][g][0], B[kk][g][1], B[kk][g][2], B[kk][g][3],
                              bB + (uint32_t)(kk * 16 * LDB + g * 16) * 2);

#pragma unroll
        for (int mi = 0; mi < 4; ++mi) {
            uint32_t A[4][4];
#pragma unroll
            for (int kk = 0; kk < 4; ++kk)
                LDMATRIX_X4(A[kk][0], A[kk][1], A[kk][2], A[kk][3],
                            aB + (uint32_t)(mi * 16 * LDA + kk * 16) * 2);
#pragma unroll
            for (int nj = 0; nj < 4; ++nj) {
                const int g = nj >> 1, p = (nj & 1) * 2;
                uint32_t d0 = 0, d1 = 0;  // fp16x2 zeros
#pragma unroll
                for (int kk = 0; kk < 4; ++kk)
                    MMA16816_F16(d0, d1, A[kk], B[kk][g][p], B[kk][g][p + 1]);
                // promote fp16 chunk result into fp32 accumulators
                float2 f01 = __half22float2(*reinterpret_cast<__half2*>(&d0));
                float2 f23 = __half22float2(*reinterpret_cast<__half2*>(&d1));
                acc[mi][nj][0] += f01.x;
                acc[mi][nj][1] += f01.y;
                acc[mi][nj][2] += f23.x;
                acc[mi][nj][3] += f23.y;
            }
        }
        if (++s_cur == STAGES) s_cur = 0;
        if (++s_nxt == STAGES) s_nxt = 0;
    }

    // ---- epilogue: direct fp32 stores ----
    const int mg = m0 + warp_m * 64 + (lane >> 2);
    const int ng = n0 + warp_n * 32 + (lane & 3) * 2;
#pragma unroll
    for (int mi = 0; mi < 4; ++mi) {
#pragma unroll
        for (int ni = 0; ni < 4; ++ni) {
            float* p0 = out + (size_t)(mg + mi * 16) * NDIM + ng + ni * 8;
            float* p1 = p0 + 8 * NDIM;
            *reinterpret_cast<float2*>(p0) = make_float2(acc[mi][ni][0], acc[mi][ni][1]);
            *reinterpret_cast<float2*>(p1) = make_float2(acc[mi][ni][2], acc[mi][ni][3]);
        }
    }
}

// ---------------------------------------------------------------------------
extern "C" void kernel_launch(void* const* d_in, const int* in_sizes, int n_in,
                              void* d_out, int out_size) {
    const float* x = (const float*)d_in[0];  // (4, 2048, 4096) fp32
    const float* w = (const float*)d_in[1];  // (4096, 4096) fp32 ternary
    float* out = (float*)d_out;              // (4, 2048, 4096) fp32

    size_t total_chunks = XCHUNKS + WCHUNKS;  // 12582912
    cvt_both_kernel<<<(int)(total_chunks / 256), 256>>>(
        reinterpret_cast<const float4*>(x), reinterpret_cast<const float4*>(w));

    cudaFuncSetAttribute(gemm_kernel, cudaFuncAttributeMaxDynamicSharedMemorySize,
                         SMEM_B);
    dim3 grid(NDIM / BN, MDIM / BM);  // (32, 64)
    gemm_kernel<<<grid, THREADS, SMEM_B>>>(out);
}